// round 11
// baseline (speedup 1.0000x reference)
#include <cuda_runtime.h>
#include <cuda_bf16.h>
#include <cstdint>

#define NFEAT  6
#define D      256
#define NPAIRS 15
#define BM     32
#define TPB    256
#define KC     16            // k-rows per pipelined chunk
#define NC     (D / KC)      // 16 chunks per 256-K GEMM

// triu_indices(6, k=1) pair order
__device__ __constant__ int cPI[NPAIRS] = {0,0,0,0,0,1,1,1,1,2,2,2,3,3,4};
__device__ __constant__ int cPJ[NPAIRS] = {1,2,3,4,5,2,3,4,5,3,4,5,4,5,5};

__device__ __forceinline__ void cp16(float* s, const float* g)
{
    unsigned int sa = (unsigned int)__cvta_generic_to_shared(s);
    asm volatile("cp.async.cg.shared.global [%0], [%1], 16;" :: "r"(sa), "l"(g));
}
#define CP_COMMIT() asm volatile("cp.async.commit_group;")
#define CP_WAIT0()  asm volatile("cp.async.wait_group 0;")

// packed f32x2 FMA: d = a*b + d (two independent fp32 FMAs, RN rounding)
__device__ __forceinline__ void fma2(unsigned long long& d,
                                     unsigned long long a,
                                     unsigned long long b)
{
    asm("fma.rn.f32x2 %0, %1, %2, %0;" : "+l"(d) : "l"(a), "l"(b));
}
__device__ __forceinline__ unsigned long long pack2(float x)
{
    unsigned long long r;
    unsigned int xb = __float_as_uint(x);
    asm("mov.b64 %0, {%1, %1};" : "=l"(r) : "r"(xb));
    return r;
}

// One 256-K GEMM: acc[8][2] (8 rows x 4 cols as packed f32x2) +=
// Asm[32][256] @ wg[256][256] (cols cbase..cbase+3 of the thread).
// cp.async double-buffered over 16-row W chunks; optionally stages Asm from
// gmem (ag) in the first cp.async group.
__device__ __forceinline__ void gemm_stage(const float* __restrict__ Asm,
                                           const float* __restrict__ wg,
                                           float*       __restrict__ sWbuf,
                                           unsigned long long acc[8][2],
                                           int tid, int mr0, int cbase,
                                           const float* __restrict__ ag)
{
    __syncthreads();                       // all warps done with prior sA/sW use
    if (ag) {                              // stage A tile (32KB contiguous)
#pragma unroll
        for (int r = 0; r < 8; r++)
            cp16((float*)Asm + 4 * (tid + r * TPB), ag + 4 * (tid + r * TPB));
    }
#pragma unroll
    for (int r = 0; r < 4; r++)            // W chunk 0 -> buf0 (16KB)
        cp16(sWbuf + 4 * (tid + r * TPB), wg + 4 * (tid + r * TPB));
    CP_COMMIT();

#pragma unroll 1
    for (int kc = 0; kc < NC; kc++) {
        CP_WAIT0();
        __syncthreads();                   // chunk kc (and A) visible; prev compute done
        if (kc + 1 < NC) {                 // prefetch chunk kc+1, overlaps mma
            float*       nb = sWbuf + ((kc + 1) & 1) * (KC * D);
            const float* ng = wg + (size_t)(kc + 1) * KC * D;
#pragma unroll
            for (int r = 0; r < 4; r++)
                cp16(nb + 4 * (tid + r * TPB), ng + 4 * (tid + r * TPB));
            CP_COMMIT();
        }
        const float* Wc = sWbuf + (kc & 1) * (KC * D);
        const int kb = kc * KC;
#pragma unroll
        for (int kk = 0; kk < KC; kk += 4) {
            float a[8][4];
#pragma unroll
            for (int i = 0; i < 8; i++) {  // warp-broadcast A reads
                float4 t = *(const float4*)(Asm + (mr0 + i) * D + kb + kk);
                a[i][0] = t.x; a[i][1] = t.y; a[i][2] = t.z; a[i][3] = t.w;
            }
#pragma unroll
            for (int kj = 0; kj < 4; kj++) {
                ulonglong2 b = *(const ulonglong2*)(Wc + (kk + kj) * D + cbase);
#pragma unroll
                for (int i = 0; i < 8; i++) {
                    unsigned long long ap = pack2(a[i][kj]);
                    fma2(acc[i][0], ap, b.x);
                    fma2(acc[i][1], ap, b.y);
                }
            }
        }
    }
}

__global__ void __launch_bounds__(TPB, 2)
cblock_kernel(const float* __restrict__ features,  // [6][M][256]
              const float* __restrict__ W_pair,    // [15][512][256]
              const float* __restrict__ b_pair,    // [15][256]
              const float* __restrict__ W_final,   // [3840][256]
              const float* __restrict__ b_final,   // [256]
              const int*   __restrict__ NAS,       // [6]
              float*       __restrict__ out,       // [M][256]
              int M)
{
    extern __shared__ float smem[];
    float* sA = smem;                     // 32 x 256 (feature tile, 32KB; sH aliases)
    float* sW = smem + BM * D;            // 2 x 16x256 (double-buffered W, 32KB)
    float* sH = sA;                       // tanh activations overwrite feature tile
    __shared__ float sMask[NPAIRS];
    __shared__ int   sNas[NFEAT];

    const int tid   = threadIdx.x;
    const int lane  = tid & 31;
    const int wid   = tid >> 5;           // 8 warps
    const int mr0   = (wid & 3) * 8;      // row group (warps w and w+4 share rows)
    const int cbase = (wid >> 2) * 128 + lane * 4;  // col half + lane cols
    const size_t m0 = (size_t)blockIdx.x * BM;

    if (tid < NFEAT) { int v = NAS[tid]; if (tid < 2) v = 1; sNas[tid] = v; }
    __syncthreads();
    if (tid < NPAIRS) sMask[tid] = (float)(sNas[cPI[tid]] * sNas[cPJ[tid]]);
    __syncthreads();

    // out accumulator (2 packed pairs x 8 rows), init with b_final
    unsigned long long oacc[8][2];
    {
        ulonglong2 f = *(const ulonglong2*)(b_final + cbase);
#pragma unroll
        for (int i = 0; i < 8; i++) { oacc[i][0] = f.x; oacc[i][1] = f.y; }
    }

#pragma unroll 1
    for (int p = 0; p < NPAIRS; p++) {
        if (sMask[p] == 0.0f) continue;   // exact: masked pair contributes zero

        // h accumulator, init with b_pair[p]
        unsigned long long hacc[8][2];
        {
            ulonglong2 b = *(const ulonglong2*)(b_pair + p * D + cbase);
#pragma unroll
            for (int i = 0; i < 8; i++) { hacc[i][0] = b.x; hacc[i][1] = b.y; }
        }

        // Stage 1: hacc += f_i @ W_top  +  f_j @ W_bot
        {
            const int fi = cPI[p], fj = cPJ[p];
            gemm_stage(sA, W_pair + (size_t)p * 2 * D * D, sW, hacc,
                       tid, mr0, cbase, features + ((size_t)fi * M + m0) * D);
            gemm_stage(sA, W_pair + ((size_t)p * 2 * D + D) * D, sW, hacc,
                       tid, mr0, cbase, features + ((size_t)fj * M + m0) * D);
        }

        // sH aliases sA: wait until ALL warps finished reading sA (both col-half
        // warps read the same rows), then write tanh.
        __syncthreads();
#pragma unroll
        for (int i = 0; i < 8; i++) {
            ulonglong2 s;
            float2 v;
            v = *reinterpret_cast<float2*>(&hacc[i][0]);
            v.x = tanhf(v.x); v.y = tanhf(v.y);
            s.x = *reinterpret_cast<unsigned long long*>(&v);
            v = *reinterpret_cast<float2*>(&hacc[i][1]);
            v.x = tanhf(v.x); v.y = tanhf(v.y);
            s.y = *reinterpret_cast<unsigned long long*>(&v);
            *(ulonglong2*)(sH + (mr0 + i) * D + cbase) = s;
        }

        // Stage 2: oacc += sH @ W_final[p*256:(p+1)*256, :]
        // (entry barrier inside gemm_stage orders tanh writes before reads)
        gemm_stage(sH, W_final + (size_t)p * D * D, sW, oacc,
                   tid, mr0, cbase, (const float*)0);
    }

    // epilogue: coalesced 16B stores
    float* orow = out + m0 * D;
#pragma unroll
    for (int i = 0; i < 8; i++) {
        ulonglong2 v;
        v.x = oacc[i][0]; v.y = oacc[i][1];
        *(ulonglong2*)(orow + (mr0 + i) * D + cbase) = v;
    }
}

extern "C" void kernel_launch(void* const* d_in, const int* in_sizes, int n_in,
                              void* d_out, int out_size)
{
    const float* features = (const float*)d_in[0];
    const float* W_pair   = (const float*)d_in[1];
    const float* b_pair   = (const float*)d_in[2];
    const float* W_final  = (const float*)d_in[3];
    const float* b_final  = (const float*)d_in[4];
    const int*   NAS      = (const int*)d_in[5];
    float*       out      = (float*)d_out;

    const int M = in_sizes[0] / (NFEAT * D);      // 16384 tokens
    const int grid = M / BM;                      // 512 blocks
    const size_t smem_bytes = ((size_t)BM * D + 2 * KC * D) * sizeof(float); // 64 KB

    cudaFuncSetAttribute(cblock_kernel,
                         cudaFuncAttributeMaxDynamicSharedMemorySize,
                         (int)smem_bytes);
    cblock_kernel<<<grid, TPB, smem_bytes>>>(features, W_pair, b_pair,
                                             W_final, b_final, NAS, out, M);
}

// round 12
// speedup vs baseline: 1.1840x; 1.1840x over previous
#include <cuda_runtime.h>
#include <cuda_bf16.h>
#include <cstdint>

#define NFEAT  6
#define D      256
#define NPAIRS 15
#define BM     32
#define TPB    256
#define KC     16            // k-rows per pipelined chunk
#define NC     (D / KC)      // 16 chunks per 256-K GEMM
#define PAD    264           // smem row stride (words): conflict-free frag loads

// triu_indices(6, k=1) pair order
__device__ __constant__ int cPI[NPAIRS] = {0,0,0,0,0,1,1,1,1,2,2,2,3,3,4};
__device__ __constant__ int cPJ[NPAIRS] = {1,2,3,4,5,2,3,4,5,3,4,5,4,5,5};

__device__ __forceinline__ void cp16(float* s, const float* g)
{
    unsigned int sa = (unsigned int)__cvta_generic_to_shared(s);
    asm volatile("cp.async.cg.shared.global [%0], [%1], 16;" :: "r"(sa), "l"(g));
}
#define CP_COMMIT() asm volatile("cp.async.commit_group;")
#define CP_WAIT0()  asm volatile("cp.async.wait_group 0;")

// m16n8k8 tf32 MMA, D += A*B (fp32 accumulate)
__device__ __forceinline__ void mma8(float d[4], const unsigned a[4],
                                     unsigned b0, unsigned b1)
{
    asm("mma.sync.aligned.m16n8k8.row.col.f32.tf32.tf32.f32 "
        "{%0,%1,%2,%3}, {%4,%5,%6,%7}, {%8,%9}, {%0,%1,%2,%3};"
        : "+f"(d[0]), "+f"(d[1]), "+f"(d[2]), "+f"(d[3])
        : "r"(a[0]), "r"(a[1]), "r"(a[2]), "r"(a[3]), "r"(b0), "r"(b1));
}
// exact hi/lo split: hi = top-19-bit truncation (valid tf32), lo = x - hi (exact)
__device__ __forceinline__ void split2(float x, unsigned& hi, unsigned& lo)
{
    hi = __float_as_uint(x) & 0xffffe000u;
    lo = __float_as_uint(x - __uint_as_float(hi));
}

// One 256-K GEMM: per-warp acc[8][4] (16x64 tile as 8 m16n8 fragments) +=
// Ap[32][256(pad 264)] @ wg[256][256] (warp cols nbw..nbw+63).
// 3xTF32: ah*bl + al*bh + ah*bh per fragment. cp.async double-buffered
// 16-row W chunks (padded rows); optionally stages Ap from gmem ag.
__device__ __forceinline__ void gemm_tc(const float* __restrict__ Ap,
                                        const float* __restrict__ wg,
                                        float*       __restrict__ sWbuf,
                                        float acc[8][4],
                                        int tid, int mrw, int nbw,
                                        int g, int tig,
                                        const float* __restrict__ ag)
{
    __syncthreads();                       // all warps done with prior smem use
    if (ag) {                              // stage A tile: 32 rows x 64 float4
#pragma unroll
        for (int r = 0; r < 8; r++) {
            int idx = tid + r * TPB, row = idx >> 6, c4 = idx & 63;
            cp16((float*)Ap + row * PAD + c4 * 4, ag + row * D + c4 * 4);
        }
    }
#pragma unroll
    for (int r = 0; r < 4; r++) {          // W chunk 0: 16 rows x 64 float4
        int idx = tid + r * TPB, row = idx >> 6, c4 = idx & 63;
        cp16(sWbuf + row * PAD + c4 * 4, wg + row * D + c4 * 4);
    }
    CP_COMMIT();

#pragma unroll 1
    for (int kc = 0; kc < NC; kc++) {
        CP_WAIT0();
        __syncthreads();                   // chunk kc (and A) visible
        if (kc + 1 < NC) {                 // prefetch next chunk, overlaps mma
            float*       nb = sWbuf + ((kc + 1) & 1) * (KC * PAD);
            const float* ng = wg + (size_t)(kc + 1) * KC * D;
#pragma unroll
            for (int r = 0; r < 4; r++) {
                int idx = tid + r * TPB, row = idx >> 6, c4 = idx & 63;
                cp16(nb + row * PAD + c4 * 4, ng + row * D + c4 * 4);
            }
            CP_COMMIT();
        }
        const float* Wc = sWbuf + (kc & 1) * (KC * PAD);
#pragma unroll
        for (int h = 0; h < 2; h++) {      // two k8 sub-chunks
            // A fragment (rows mrw+g, mrw+g+8; cols k..k+7)
            const float* ap = Ap + (mrw + g) * PAD + kc * KC + h * 8 + tig;
            unsigned ah[4], al[4];
            split2(ap[0],           ah[0], al[0]);
            split2(ap[8 * PAD],     ah[1], al[1]);
            split2(ap[4],           ah[2], al[2]);
            split2(ap[8 * PAD + 4], ah[3], al[3]);
            const float* bp = Wc + (h * 8 + tig) * PAD + nbw + g;
#pragma unroll
            for (int t = 0; t < 8; t++) {  // 8 n8 fragments
                unsigned bh0, bl0, bh1, bl1;
                split2(bp[t * 8],           bh0, bl0);
                split2(bp[t * 8 + 4 * PAD], bh1, bl1);
                mma8(acc[t], ah, bl0, bl1);   // small terms first
                mma8(acc[t], al, bh0, bh1);
                mma8(acc[t], ah, bh0, bh1);
            }
        }
    }
}

__global__ void __launch_bounds__(TPB, 2)
cblock_kernel(const float* __restrict__ features,  // [6][M][256]
              const float* __restrict__ W_pair,    // [15][512][256]
              const float* __restrict__ b_pair,    // [15][256]
              const float* __restrict__ W_final,   // [3840][256]
              const float* __restrict__ b_final,   // [256]
              const int*   __restrict__ NAS,       // [6]
              float*       __restrict__ out,       // [M][256]
              int M)
{
    extern __shared__ float smem[];
    float* sA = smem;                     // 32 x 264 (feature tile; sH aliases)
    float* sW = smem + BM * PAD;          // 2 x 16 x 264 (double-buffered W)
    float* sH = sA;                       // tanh activations overwrite features
    __shared__ float sMask[NPAIRS];
    __shared__ int   sNas[NFEAT];

    const int tid  = threadIdx.x;
    const int lane = tid & 31;
    const int wid  = tid >> 5;            // 8 warps
    const int g    = lane >> 2;           // fragment groupID (0..7)
    const int tig  = lane & 3;            // thread-in-group (0..3)
    const int mrw  = (wid & 1) * 16;      // warp row base (2 m-tiles)
    const int nbw  = (wid >> 1) * 64;     // warp col base (4 n-tiles)
    const size_t m0 = (size_t)blockIdx.x * BM;

    if (tid < NFEAT) { int v = NAS[tid]; if (tid < 2) v = 1; sNas[tid] = v; }
    __syncthreads();
    if (tid < NPAIRS) sMask[tid] = (float)(sNas[cPI[tid]] * sNas[cPJ[tid]]);
    __syncthreads();

    // out accumulator fragments, init with b_final (same bias both frag rows)
    float oacc[8][4];
#pragma unroll
    for (int t = 0; t < 8; t++) {
        float2 b = *(const float2*)(b_final + nbw + t * 8 + 2 * tig);
        oacc[t][0] = b.x; oacc[t][1] = b.y; oacc[t][2] = b.x; oacc[t][3] = b.y;
    }

#pragma unroll 1
    for (int p = 0; p < NPAIRS; p++) {
        if (sMask[p] == 0.0f) continue;   // exact: masked pair contributes zero

        // h accumulator fragments, init with b_pair[p]
        float hacc[8][4];
#pragma unroll
        for (int t = 0; t < 8; t++) {
            float2 b = *(const float2*)(b_pair + p * D + nbw + t * 8 + 2 * tig);
            hacc[t][0] = b.x; hacc[t][1] = b.y; hacc[t][2] = b.x; hacc[t][3] = b.y;
        }

        // Stage 1: hacc += f_i @ W_top  +  f_j @ W_bot
        {
            const int fi = cPI[p], fj = cPJ[p];
            gemm_tc(sA, W_pair + (size_t)p * 2 * D * D, sW, hacc,
                    tid, mrw, nbw, g, tig, features + ((size_t)fi * M + m0) * D);
            gemm_tc(sA, W_pair + ((size_t)p * 2 * D + D) * D, sW, hacc,
                    tid, mrw, nbw, g, tig, features + ((size_t)fj * M + m0) * D);
        }

        // sH aliases sA: wait for all warps to finish reading sA, then write
        // tanh in C-fragment layout (row g / g+8, cols 2tig, 2tig+1).
        __syncthreads();
#pragma unroll
        for (int t = 0; t < 8; t++) {
            float2 v0, v1;
            v0.x = tanhf(hacc[t][0]); v0.y = tanhf(hacc[t][1]);
            v1.x = tanhf(hacc[t][2]); v1.y = tanhf(hacc[t][3]);
            *(float2*)(sH + (mrw + g)     * PAD + nbw + t * 8 + 2 * tig) = v0;
            *(float2*)(sH + (mrw + g + 8) * PAD + nbw + t * 8 + 2 * tig) = v1;
        }

        // Stage 2: oacc += sH @ W_final[p*256:(p+1)*256, :]
        // (entry barrier inside gemm_tc orders tanh writes before reads)
        gemm_tc(sH, W_final + (size_t)p * D * D, sW, oacc,
                tid, mrw, nbw, g, tig, (const float*)0);
    }

    // epilogue: fragment stores (float2 per row) to gmem
    float* orow = out + m0 * D;
#pragma unroll
    for (int t = 0; t < 8; t++) {
        float2 v0, v1;
        v0.x = oacc[t][0]; v0.y = oacc[t][1];
        v1.x = oacc[t][2]; v1.y = oacc[t][3];
        *(float2*)(orow + (mrw + g)     * D + nbw + t * 8 + 2 * tig) = v0;
        *(float2*)(orow + (mrw + g + 8) * D + nbw + t * 8 + 2 * tig) = v1;
    }
}

extern "C" void kernel_launch(void* const* d_in, const int* in_sizes, int n_in,
                              void* d_out, int out_size)
{
    const float* features = (const float*)d_in[0];
    const float* W_pair   = (const float*)d_in[1];
    const float* b_pair   = (const float*)d_in[2];
    const float* W_final  = (const float*)d_in[3];
    const float* b_final  = (const float*)d_in[4];
    const int*   NAS      = (const int*)d_in[5];
    float*       out      = (float*)d_out;

    const int M = in_sizes[0] / (NFEAT * D);      // 16384 tokens
    const int grid = M / BM;                      // 512 blocks
    const size_t smem_bytes = ((size_t)BM * PAD + 2 * KC * PAD) * sizeof(float); // ~66 KB

    cudaFuncSetAttribute(cblock_kernel,
                         cudaFuncAttributeMaxDynamicSharedMemorySize,
                         (int)smem_bytes);
    cblock_kernel<<<grid, TPB, smem_bytes>>>(features, W_pair, b_pair,
                                             W_final, b_final, NAS, out, M);
}

// round 13
// speedup vs baseline: 1.7021x; 1.4377x over previous
#include <cuda_runtime.h>
#include <cuda_bf16.h>
#include <cstdint>

#define NFEAT  6
#define D      256
#define NPAIRS 15
#define BM     32
#define TPB    256
#define KC     16            // k per chunk
#define NC     16            // chunks per 256-K GEMM
#define PADA   264           // fp32 A tile row stride (words)
#define PADW   264           // packed W chunk row stride (words)
#define PADH   132           // packed H (hi/lo) row stride (words)

#define WPAIR_ELEMS (15 * 256 * 256)   // packed kp x n  (512 k -> 256 kp)
#define WFIN_ELEMS  (15 * 128 * 256)   // 256 k -> 128 kp

// pre-split bf16 weight scratch (hi/lo packed bf16x2 per k-pair)
__device__ unsigned g_Whi[WPAIR_ELEMS + WFIN_ELEMS];
__device__ unsigned g_Wlo[WPAIR_ELEMS + WFIN_ELEMS];

// triu_indices(6, k=1) pair order
__device__ __constant__ int cPI[NPAIRS] = {0,0,0,0,0,1,1,1,1,2,2,2,3,3,4};
__device__ __constant__ int cPJ[NPAIRS] = {1,2,3,4,5,2,3,4,5,3,4,5,4,5,5};

__device__ __forceinline__ void cp16(void* s, const void* g)
{
    unsigned int sa = (unsigned int)__cvta_generic_to_shared(s);
    asm volatile("cp.async.cg.shared.global [%0], [%1], 16;" :: "r"(sa), "l"(g));
}
#define CP_COMMIT() asm volatile("cp.async.commit_group;")
#define CP_WAIT0()  asm volatile("cp.async.wait_group 0;")

// m16n8k16 bf16 MMA, D += A*B (fp32 accumulate)
__device__ __forceinline__ void mmab(float d[4], const unsigned a[4],
                                     unsigned b0, unsigned b1)
{
    asm("mma.sync.aligned.m16n8k16.row.col.f32.bf16.bf16.f32 "
        "{%0,%1,%2,%3}, {%4,%5,%6,%7}, {%8,%9}, {%0,%1,%2,%3};"
        : "+f"(d[0]), "+f"(d[1]), "+f"(d[2]), "+f"(d[3])
        : "r"(a[0]), "r"(a[1]), "r"(a[2]), "r"(a[3]), "r"(b0), "r"(b1));
}

// split fp32 pair -> packed bf16x2 hi (truncate) + lo (exact residual, RN)
__device__ __forceinline__ void packpair(float2 v, unsigned& hi, unsigned& lo)
{
    unsigned ux = __float_as_uint(v.x), uy = __float_as_uint(v.y);
    hi = __byte_perm(ux, uy, 0x7632);                 // {bf16(v.x), bf16(v.y)}
    float lx = v.x - __uint_as_float(ux & 0xffff0000u);
    float ly = v.y - __uint_as_float(uy & 0xffff0000u);
    asm("cvt.rn.bf16x2.f32 %0, %1, %2;" : "=r"(lo) : "f"(ly), "f"(lx));
}

// Prepass: split active-pair weights into packed bf16 hi/lo k-pair layout.
__global__ void prep_kernel(const float* __restrict__ W_pair,
                            const float* __restrict__ W_final,
                            const int*   __restrict__ NAS)
{
    int idx = blockIdx.x * TPB + threadIdx.x;
    int p;
    const float* src;
    if (idx < WPAIR_ELEMS) {
        p = idx >> 16;                               // 65536 per pair
        int rem = idx & 65535, kp = rem >> 8, n = rem & 255;
        src = W_pair + (size_t)p * 131072 + kp * 512 + n;   // rows 2kp, 2kp+1
    } else {
        int idx2 = idx - WPAIR_ELEMS;
        p = idx2 >> 15;                              // 32768 per pair
        int rem = idx2 & 32767, kp = rem >> 8, n = rem & 255;
        src = W_final + (size_t)p * 65536 + kp * 512 + n;
    }
    int fi = cPI[p], fj = cPJ[p];
    int vi = (fi < 2) ? 1 : NAS[fi];
    int vj = (fj < 2) ? 1 : NAS[fj];
    if (vi * vj == 0) return;                        // inactive: never read
    float2 v; v.x = src[0]; v.y = src[256];
    unsigned hi, lo;
    packpair(v, hi, lo);
    g_Whi[idx] = hi; g_Wlo[idx] = lo;
}

// One 256-K GEMM. acc = 8 m16n8 fragments (warp tile 16x64).
// PA=false: A from fp32 smem tile (split in-loop), optionally staged from ag.
// PA=true:  A from pre-packed sAhi/sAlo (tanh output).
// B from pre-split gmem scratch via cp.async double-buffered 8-kp chunks.
template<bool PA>
__device__ __forceinline__ void gemm_tc(const float* __restrict__ sAf,
                                        const unsigned* __restrict__ sAhi,
                                        const unsigned* __restrict__ sAlo,
                                        const unsigned* __restrict__ wHi,
                                        const unsigned* __restrict__ wLo,
                                        unsigned* __restrict__ sWb,
                                        float acc[8][4],
                                        int tid, int mrw, int nbw,
                                        int g, int tig,
                                        const float* __restrict__ ag)
{
    __syncthreads();                       // all warps done with prior smem use
    if (!PA && ag) {                       // stage fp32 A tile 32x256 -> padded
#pragma unroll
        for (int r = 0; r < 8; r++) {
            int idx = tid + r * TPB, row = idx >> 6, c4 = idx & 63;
            cp16((float*)sAf + row * PADA + c4 * 4, ag + row * D + c4 * 4);
        }
    }
#pragma unroll
    for (int r = 0; r < 2; r++) {          // W chunk 0 (hi + lo, 8 kp rows)
        int idx = tid + r * TPB, row = idx >> 6, c4 = idx & 63;
        cp16(sWb + row * PADW + c4 * 4,            wHi + row * 256 + c4 * 4);
        cp16(sWb + 8 * PADW + row * PADW + c4 * 4, wLo + row * 256 + c4 * 4);
    }
    CP_COMMIT();

#pragma unroll 1
    for (int kc = 0; kc < NC; kc++) {
        CP_WAIT0();
        __syncthreads();                   // chunk kc (and A) visible
        if (kc + 1 < NC) {                 // prefetch next chunk, overlaps mma
            unsigned* nb = sWb + ((kc + 1) & 1) * (16 * PADW);
            const unsigned* nhi = wHi + (kc + 1) * 2048;
            const unsigned* nlo = wLo + (kc + 1) * 2048;
#pragma unroll
            for (int r = 0; r < 2; r++) {
                int idx = tid + r * TPB, row = idx >> 6, c4 = idx & 63;
                cp16(nb + row * PADW + c4 * 4,            nhi + row * 256 + c4 * 4);
                cp16(nb + 8 * PADW + row * PADW + c4 * 4, nlo + row * 256 + c4 * 4);
            }
            CP_COMMIT();
        }
        const unsigned* Whic = sWb + (kc & 1) * (16 * PADW);
        const unsigned* Wloc = Whic + 8 * PADW;

        unsigned Ahi[4], Alo[4];
        if (PA) {
            const unsigned* ph = sAhi + (mrw + g) * PADH + kc * 8 + tig;
            const unsigned* pl = sAlo + (mrw + g) * PADH + kc * 8 + tig;
            Ahi[0] = ph[0]; Ahi[1] = ph[8 * PADH];
            Ahi[2] = ph[4]; Ahi[3] = ph[8 * PADH + 4];
            Alo[0] = pl[0]; Alo[1] = pl[8 * PADH];
            Alo[2] = pl[4]; Alo[3] = pl[8 * PADH + 4];
        } else {
            const float* ap = sAf + (mrw + g) * PADA + kc * KC + 2 * tig;
            packpair(*(const float2*)(ap),                Ahi[0], Alo[0]);
            packpair(*(const float2*)(ap + 8 * PADA),     Ahi[1], Alo[1]);
            packpair(*(const float2*)(ap + 8),            Ahi[2], Alo[2]);
            packpair(*(const float2*)(ap + 8 * PADA + 8), Ahi[3], Alo[3]);
        }
#pragma unroll
        for (int t = 0; t < 8; t++) {
            int n = nbw + t * 8 + g;
            unsigned b0h = Whic[tig * PADW + n];
            unsigned b1h = Whic[(tig + 4) * PADW + n];
            unsigned b0l = Wloc[tig * PADW + n];
            unsigned b1l = Wloc[(tig + 4) * PADW + n];
            mmab(acc[t], Ahi, b0l, b1l);   // cross terms first
            mmab(acc[t], Alo, b0h, b1h);
            mmab(acc[t], Ahi, b0h, b1h);   // main term
        }
    }
}

__global__ void __launch_bounds__(TPB, 2)
cblock_kernel(const float* __restrict__ features,  // [6][M][256]
              const float* __restrict__ b_pair,    // [15][256]
              const float* __restrict__ b_final,   // [256]
              const int*   __restrict__ NAS,       // [6]
              float*       __restrict__ out,       // [M][256]
              int M)
{
    extern __shared__ float smem[];
    float*    sA   = smem;                              // 32x264 fp32 (33792B)
    unsigned* sHhi = (unsigned*)smem;                   // aliases sA: 32x132
    unsigned* sHlo = (unsigned*)smem + BM * PADH;       // 32x132 (same 33792B)
    unsigned* sW   = (unsigned*)(smem + BM * PADA);     // 2 x (16*264) = 33792B
    __shared__ float sMask[NPAIRS];
    __shared__ int   sNas[NFEAT];

    const int tid  = threadIdx.x;
    const int lane = tid & 31;
    const int wid  = tid >> 5;            // 8 warps
    const int g    = lane >> 2;           // fragment groupID (0..7)
    const int tig  = lane & 3;            // thread-in-group (0..3)
    const int mrw  = (wid & 1) * 16;      // warp row base (2 m-tiles)
    const int nbw  = (wid >> 1) * 64;     // warp col base (4 n-tiles)
    const size_t m0 = (size_t)blockIdx.x * BM;

    if (tid < NFEAT) { int v = NAS[tid]; if (tid < 2) v = 1; sNas[tid] = v; }
    __syncthreads();
    if (tid < NPAIRS) sMask[tid] = (float)(sNas[cPI[tid]] * sNas[cPJ[tid]]);
    __syncthreads();

    // out accumulator fragments, init with b_final
    float oacc[8][4];
#pragma unroll
    for (int t = 0; t < 8; t++) {
        float2 b = *(const float2*)(b_final + nbw + t * 8 + 2 * tig);
        oacc[t][0] = b.x; oacc[t][1] = b.y; oacc[t][2] = b.x; oacc[t][3] = b.y;
    }

#pragma unroll 1
    for (int p = 0; p < NPAIRS; p++) {
        if (sMask[p] == 0.0f) continue;   // exact: masked pair contributes zero

        float hacc[8][4];
#pragma unroll
        for (int t = 0; t < 8; t++) {
            float2 b = *(const float2*)(b_pair + p * D + nbw + t * 8 + 2 * tig);
            hacc[t][0] = b.x; hacc[t][1] = b.y; hacc[t][2] = b.x; hacc[t][3] = b.y;
        }

        // Stage 1: hacc += f_i @ W_top  +  f_j @ W_bot   (pre-split weights)
        {
            const int fi = cPI[p], fj = cPJ[p];
            const unsigned* whi = g_Whi + (size_t)p * 65536;
            const unsigned* wlo = g_Wlo + (size_t)p * 65536;
            gemm_tc<false>(sA, 0, 0, whi, wlo, sW, hacc,
                           tid, mrw, nbw, g, tig,
                           features + ((size_t)fi * M + m0) * D);
            gemm_tc<false>(sA, 0, 0, whi + 32768, wlo + 32768, sW, hacc,
                           tid, mrw, nbw, g, tig,
                           features + ((size_t)fj * M + m0) * D);
        }

        // tanh -> packed hi/lo pairs in sH (aliases sA); barrier first: other
        // warps may still read sA in their last chunk.
        __syncthreads();
#pragma unroll
        for (int t = 0; t < 8; t++) {
            int kpb = (nbw >> 1) + 4 * t + tig;
            float2 v0, v1;
            v0.x = tanhf(hacc[t][0]); v0.y = tanhf(hacc[t][1]);
            v1.x = tanhf(hacc[t][2]); v1.y = tanhf(hacc[t][3]);
            unsigned h0, l0, h1, l1;
            packpair(v0, h0, l0);
            packpair(v1, h1, l1);
            sHhi[(mrw + g)     * PADH + kpb] = h0;
            sHlo[(mrw + g)     * PADH + kpb] = l0;
            sHhi[(mrw + g + 8) * PADH + kpb] = h1;
            sHlo[(mrw + g + 8) * PADH + kpb] = l1;
        }

        // Stage 2: oacc += h @ W_final[p]   (A pre-packed; entry barrier
        // inside gemm_tc orders tanh writes before reads)
        {
            const unsigned* whi = g_Whi + WPAIR_ELEMS + (size_t)p * 32768;
            const unsigned* wlo = g_Wlo + WPAIR_ELEMS + (size_t)p * 32768;
            gemm_tc<true>(0, sHhi, sHlo, whi, wlo, sW, oacc,
                          tid, mrw, nbw, g, tig, (const float*)0);
        }
    }

    // epilogue: fragment stores
    float* orow = out + m0 * D;
#pragma unroll
    for (int t = 0; t < 8; t++) {
        float2 v0, v1;
        v0.x = oacc[t][0]; v0.y = oacc[t][1];
        v1.x = oacc[t][2]; v1.y = oacc[t][3];
        *(float2*)(orow + (mrw + g)     * D + nbw + t * 8 + 2 * tig) = v0;
        *(float2*)(orow + (mrw + g + 8) * D + nbw + t * 8 + 2 * tig) = v1;
    }
}

extern "C" void kernel_launch(void* const* d_in, const int* in_sizes, int n_in,
                              void* d_out, int out_size)
{
    const float* features = (const float*)d_in[0];
    const float* W_pair   = (const float*)d_in[1];
    const float* b_pair   = (const float*)d_in[2];
    const float* W_final  = (const float*)d_in[3];
    const float* b_final  = (const float*)d_in[4];
    const int*   NAS      = (const int*)d_in[5];
    float*       out      = (float*)d_out;

    const int M = in_sizes[0] / (NFEAT * D);      // 16384 tokens

    // prepass: split weights of active pairs into bf16 hi/lo scratch
    prep_kernel<<<(WPAIR_ELEMS + WFIN_ELEMS) / TPB, TPB>>>(W_pair, W_final, NAS);

    const int grid = M / BM;                      // 512 blocks
    const size_t smem_bytes = ((size_t)BM * PADA + 2 * 16 * PADW) * sizeof(float);

    cudaFuncSetAttribute(cblock_kernel,
                         cudaFuncAttributeMaxDynamicSharedMemorySize,
                         (int)smem_bytes);
    cblock_kernel<<<grid, TPB, smem_bytes>>>(features, b_pair,
                                             b_final, NAS, out, M);
}

// round 14
// speedup vs baseline: 1.7454x; 1.0254x over previous
#include <cuda_runtime.h>
#include <cuda_bf16.h>
#include <cstdint>

#define NFEAT  6
#define D      256
#define NPAIRS 15
#define BM     32
#define TPB    256
#define KC     16            // k per chunk
#define NC     16            // chunks per 256-K GEMM
#define PADA   264           // fp32 A tile row stride (words)
#define PADW   264           // packed W chunk row stride (words)
#define PADH   132           // packed H (hi/lo) row stride (words)
#define NSTAGE 3             // cp.async ring depth

#define WPAIR_ELEMS (15 * 256 * 256)   // packed kp x n  (512 k -> 256 kp)
#define WFIN_ELEMS  (15 * 128 * 256)   // 256 k -> 128 kp

// pre-split bf16 weight scratch (hi/lo packed bf16x2 per k-pair)
__device__ unsigned g_Whi[WPAIR_ELEMS + WFIN_ELEMS];
__device__ unsigned g_Wlo[WPAIR_ELEMS + WFIN_ELEMS];

// triu_indices(6, k=1) pair order
__device__ __constant__ int cPI[NPAIRS] = {0,0,0,0,0,1,1,1,1,2,2,2,3,3,4};
__device__ __constant__ int cPJ[NPAIRS] = {1,2,3,4,5,2,3,4,5,3,4,5,4,5,5};

__device__ __forceinline__ void cp16(void* s, const void* g)
{
    unsigned int sa = (unsigned int)__cvta_generic_to_shared(s);
    asm volatile("cp.async.cg.shared.global [%0], [%1], 16;" :: "r"(sa), "l"(g));
}
#define CP_COMMIT() asm volatile("cp.async.commit_group;")
#define CP_WAIT0()  asm volatile("cp.async.wait_group 0;")
#define CP_WAIT1()  asm volatile("cp.async.wait_group 1;")

// m16n8k16 bf16 MMA, D += A*B (fp32 accumulate)
__device__ __forceinline__ void mmab(float d[4], const unsigned a[4],
                                     unsigned b0, unsigned b1)
{
    asm("mma.sync.aligned.m16n8k16.row.col.f32.bf16.bf16.f32 "
        "{%0,%1,%2,%3}, {%4,%5,%6,%7}, {%8,%9}, {%0,%1,%2,%3};"
        : "+f"(d[0]), "+f"(d[1]), "+f"(d[2]), "+f"(d[3])
        : "r"(a[0]), "r"(a[1]), "r"(a[2]), "r"(a[3]), "r"(b0), "r"(b1));
}

// split fp32 pair -> packed bf16x2 hi (truncate) + lo (exact residual, RN)
__device__ __forceinline__ void packpair(float2 v, unsigned& hi, unsigned& lo)
{
    unsigned ux = __float_as_uint(v.x), uy = __float_as_uint(v.y);
    hi = __byte_perm(ux, uy, 0x7632);                 // {bf16(v.x), bf16(v.y)}
    float lx = v.x - __uint_as_float(ux & 0xffff0000u);
    float ly = v.y - __uint_as_float(uy & 0xffff0000u);
    asm("cvt.rn.bf16x2.f32 %0, %1, %2;" : "=r"(lo) : "f"(ly), "f"(lx));
}

// Prepass: split active-pair weights into packed bf16 hi/lo k-pair layout.
__global__ void prep_kernel(const float* __restrict__ W_pair,
                            const float* __restrict__ W_final,
                            const int*   __restrict__ NAS)
{
    int idx = blockIdx.x * TPB + threadIdx.x;
    int p;
    const float* src;
    if (idx < WPAIR_ELEMS) {
        p = idx >> 16;                               // 65536 per pair
        int rem = idx & 65535, kp = rem >> 8, n = rem & 255;
        src = W_pair + (size_t)p * 131072 + kp * 512 + n;   // rows 2kp, 2kp+1
    } else {
        int idx2 = idx - WPAIR_ELEMS;
        p = idx2 >> 15;                              // 32768 per pair
        int rem = idx2 & 32767, kp = rem >> 8, n = rem & 255;
        src = W_final + (size_t)p * 65536 + kp * 512 + n;
    }
    int fi = cPI[p], fj = cPJ[p];
    int vi = (fi < 2) ? 1 : NAS[fi];
    int vj = (fj < 2) ? 1 : NAS[fj];
    if (vi * vj == 0) return;                        // inactive: never read
    float2 v; v.x = src[0]; v.y = src[256];
    unsigned hi, lo;
    packpair(v, hi, lo);
    g_Whi[idx] = hi; g_Wlo[idx] = lo;
}

// stage one 8-kp W chunk (hi+lo) into ring slot
__device__ __forceinline__ void stage_chunk(unsigned* __restrict__ slot,
                                            const unsigned* __restrict__ wHi,
                                            const unsigned* __restrict__ wLo,
                                            int kc, int tid)
{
    const unsigned* hi = wHi + kc * 2048;
    const unsigned* lo = wLo + kc * 2048;
#pragma unroll
    for (int r = 0; r < 2; r++) {
        int idx = tid + r * TPB, row = idx >> 6, c4 = idx & 63;
        cp16(slot + row * PADW + c4 * 4,            hi + row * 256 + c4 * 4);
        cp16(slot + 8 * PADW + row * PADW + c4 * 4, lo + row * 256 + c4 * 4);
    }
    CP_COMMIT();
}

// One 256-K GEMM. acc = 8 m16n8 fragments (warp tile 16x64).
// PA=false: A from fp32 smem tile (split in-loop), optionally staged from ag.
// PA=true:  A from pre-packed sAhi/sAlo (tanh output).
// B streamed through a 3-stage cp.async ring (wait_group 1 -> prefetch runs
// two chunks ahead; full drain only on the final chunk).
template<bool PA>
__device__ __forceinline__ void gemm_tc(const float* __restrict__ sAf,
                                        const unsigned* __restrict__ sAhi,
                                        const unsigned* __restrict__ sAlo,
                                        const unsigned* __restrict__ wHi,
                                        const unsigned* __restrict__ wLo,
                                        unsigned* __restrict__ sWb,
                                        float acc[8][4],
                                        int tid, int mrw, int nbw,
                                        int g, int tig,
                                        const float* __restrict__ ag)
{
    __syncthreads();                       // all warps done with prior smem use
    if (!PA && ag) {                       // stage fp32 A tile 32x256 -> padded
#pragma unroll
        for (int r = 0; r < 8; r++) {
            int idx = tid + r * TPB, row = idx >> 6, c4 = idx & 63;
            cp16((float*)sAf + row * PADA + c4 * 4, ag + row * D + c4 * 4);
        }
    }
    stage_chunk(sWb,              wHi, wLo, 0, tid);   // group: {A?, chunk0}
    stage_chunk(sWb + 16 * PADW,  wHi, wLo, 1, tid);   // group: {chunk1}

#pragma unroll 1
    for (int kc = 0; kc < NC; kc++) {
        if (kc + 1 < NC) CP_WAIT1();       // chunk kc done, kc+1 may fly
        else             CP_WAIT0();       // last chunk: nothing newer, drain
        __syncthreads();                   // chunk kc (and A) visible to all
        if (kc + 2 < NC)                   // prefetch kc+2 into slot (kc+2)%3
            stage_chunk(sWb + ((kc + 2) % NSTAGE) * (16 * PADW), wHi, wLo,
                        kc + 2, tid);
        const unsigned* Whic = sWb + (kc % NSTAGE) * (16 * PADW);
        const unsigned* Wloc = Whic + 8 * PADW;

        unsigned Ahi[4], Alo[4];
        if (PA) {
            const unsigned* ph = sAhi + (mrw + g) * PADH + kc * 8 + tig;
            const unsigned* pl = sAlo + (mrw + g) * PADH + kc * 8 + tig;
            Ahi[0] = ph[0]; Ahi[1] = ph[8 * PADH];
            Ahi[2] = ph[4]; Ahi[3] = ph[8 * PADH + 4];
            Alo[0] = pl[0]; Alo[1] = pl[8 * PADH];
            Alo[2] = pl[4]; Alo[3] = pl[8 * PADH + 4];
        } else {
            const float* ap = sAf + (mrw + g) * PADA + kc * KC + 2 * tig;
            packpair(*(const float2*)(ap),                Ahi[0], Alo[0]);
            packpair(*(const float2*)(ap + 8 * PADA),     Ahi[1], Alo[1]);
            packpair(*(const float2*)(ap + 8),            Ahi[2], Alo[2]);
            packpair(*(const float2*)(ap + 8 * PADA + 8), Ahi[3], Alo[3]);
        }
#pragma unroll
        for (int t = 0; t < 8; t++) {
            int n = nbw + t * 8 + g;
            unsigned b0h = Whic[tig * PADW + n];
            unsigned b1h = Whic[(tig + 4) * PADW + n];
            unsigned b0l = Wloc[tig * PADW + n];
            unsigned b1l = Wloc[(tig + 4) * PADW + n];
            mmab(acc[t], Ahi, b0l, b1l);   // cross terms first
            mmab(acc[t], Alo, b0h, b1h);
            mmab(acc[t], Ahi, b0h, b1h);   // main term
        }
    }
}

__global__ void __launch_bounds__(TPB, 2)
cblock_kernel(const float* __restrict__ features,  // [6][M][256]
              const float* __restrict__ b_pair,    // [15][256]
              const float* __restrict__ b_final,   // [256]
              const int*   __restrict__ NAS,       // [6]
              float*       __restrict__ out,       // [M][256]
              int M)
{
    extern __shared__ float smem[];
    float*    sA   = smem;                              // 32x264 fp32 (33792B)
    unsigned* sHhi = (unsigned*)smem;                   // aliases sA: 32x132
    unsigned* sHlo = (unsigned*)smem + BM * PADH;       // 32x132 (same 33792B)
    unsigned* sW   = (unsigned*)(smem + BM * PADA);     // 3 x (16*264) ring
    __shared__ float sMask[NPAIRS];
    __shared__ int   sNas[NFEAT];

    const int tid  = threadIdx.x;
    const int lane = tid & 31;
    const int wid  = tid >> 5;            // 8 warps
    const int g    = lane >> 2;           // fragment groupID (0..7)
    const int tig  = lane & 3;            // thread-in-group (0..3)
    const int mrw  = (wid & 1) * 16;      // warp row base (2 m-tiles)
    const int nbw  = (wid >> 1) * 64;     // warp col base (4 n-tiles)
    const size_t m0 = (size_t)blockIdx.x * BM;

    if (tid < NFEAT) { int v = NAS[tid]; if (tid < 2) v = 1; sNas[tid] = v; }
    __syncthreads();
    if (tid < NPAIRS) sMask[tid] = (float)(sNas[cPI[tid]] * sNas[cPJ[tid]]);
    __syncthreads();

    // out accumulator fragments, init with b_final
    float oacc[8][4];
#pragma unroll
    for (int t = 0; t < 8; t++) {
        float2 b = *(const float2*)(b_final + nbw + t * 8 + 2 * tig);
        oacc[t][0] = b.x; oacc[t][1] = b.y; oacc[t][2] = b.x; oacc[t][3] = b.y;
    }

#pragma unroll 1
    for (int p = 0; p < NPAIRS; p++) {
        if (sMask[p] == 0.0f) continue;   // exact: masked pair contributes zero

        float hacc[8][4];
#pragma unroll
        for (int t = 0; t < 8; t++) {
            float2 b = *(const float2*)(b_pair + p * D + nbw + t * 8 + 2 * tig);
            hacc[t][0] = b.x; hacc[t][1] = b.y; hacc[t][2] = b.x; hacc[t][3] = b.y;
        }

        // Stage 1: hacc += f_i @ W_top  +  f_j @ W_bot   (pre-split weights)
        {
            const int fi = cPI[p], fj = cPJ[p];
            const unsigned* whi = g_Whi + (size_t)p * 65536;
            const unsigned* wlo = g_Wlo + (size_t)p * 65536;
            gemm_tc<false>(sA, 0, 0, whi, wlo, sW, hacc,
                           tid, mrw, nbw, g, tig,
                           features + ((size_t)fi * M + m0) * D);
            gemm_tc<false>(sA, 0, 0, whi + 32768, wlo + 32768, sW, hacc,
                           tid, mrw, nbw, g, tig,
                           features + ((size_t)fj * M + m0) * D);
        }

        // tanh -> packed hi/lo pairs in sH (aliases sA); barrier first: other
        // warps may still read sA in their last chunk.
        __syncthreads();
#pragma unroll
        for (int t = 0; t < 8; t++) {
            int kpb = (nbw >> 1) + 4 * t + tig;
            float2 v0, v1;
            v0.x = tanhf(hacc[t][0]); v0.y = tanhf(hacc[t][1]);
            v1.x = tanhf(hacc[t][2]); v1.y = tanhf(hacc[t][3]);
            unsigned h0, l0, h1, l1;
            packpair(v0, h0, l0);
            packpair(v1, h1, l1);
            sHhi[(mrw + g)     * PADH + kpb] = h0;
            sHlo[(mrw + g)     * PADH + kpb] = l0;
            sHhi[(mrw + g + 8) * PADH + kpb] = h1;
            sHlo[(mrw + g + 8) * PADH + kpb] = l1;
        }

        // Stage 2: oacc += h @ W_final[p]   (A pre-packed; entry barrier
        // inside gemm_tc orders tanh writes before reads)
        {
            const unsigned* whi = g_Whi + WPAIR_ELEMS + (size_t)p * 32768;
            const unsigned* wlo = g_Wlo + WPAIR_ELEMS + (size_t)p * 32768;
            gemm_tc<true>(0, sHhi, sHlo, whi, wlo, sW, oacc,
                          tid, mrw, nbw, g, tig, (const float*)0);
        }
    }

    // epilogue: fragment stores
    float* orow = out + m0 * D;
#pragma unroll
    for (int t = 0; t < 8; t++) {
        float2 v0, v1;
        v0.x = oacc[t][0]; v0.y = oacc[t][1];
        v1.x = oacc[t][2]; v1.y = oacc[t][3];
        *(float2*)(orow + (mrw + g)     * D + nbw + t * 8 + 2 * tig) = v0;
        *(float2*)(orow + (mrw + g + 8) * D + nbw + t * 8 + 2 * tig) = v1;
    }
}

extern "C" void kernel_launch(void* const* d_in, const int* in_sizes, int n_in,
                              void* d_out, int out_size)
{
    const float* features = (const float*)d_in[0];
    const float* W_pair   = (const float*)d_in[1];
    const float* b_pair   = (const float*)d_in[2];
    const float* W_final  = (const float*)d_in[3];
    const float* b_final  = (const float*)d_in[4];
    const int*   NAS      = (const int*)d_in[5];
    float*       out      = (float*)d_out;

    const int M = in_sizes[0] / (NFEAT * D);      // 16384 tokens

    // prepass: split weights of active pairs into bf16 hi/lo scratch
    prep_kernel<<<(WPAIR_ELEMS + WFIN_ELEMS) / TPB, TPB>>>(W_pair, W_final, NAS);

    const int grid = M / BM;                      // 512 blocks
    const size_t smem_bytes = ((size_t)BM * PADA + NSTAGE * 16 * PADW)
                              * sizeof(float);    // ~82.5 KB

    cudaFuncSetAttribute(cblock_kernel,
                         cudaFuncAttributeMaxDynamicSharedMemorySize,
                         (int)smem_bytes);
    cblock_kernel<<<grid, TPB, smem_bytes>>>(features, b_pair,
                                             b_final, NAS, out, M);
}